// round 4
// baseline (speedup 1.0000x reference)
#include <cuda_runtime.h>
#include <cuda_bf16.h>
#include <cfloat>

// Problem constants
#define NN   256      // nodes
#define FF   255      // feature dim
#define FF2  510      // 2*F
#define EE   65536    // edges
#define HH   2048     // hidden
#define OUTN 32640    // output
#define NF   65280    // N*F (flatten)

// ---------------- scratch (__device__ globals, no runtime alloc) -------------
__device__ __align__(16) float g_T[3 * FF * FF2];    // W2@W1 per layer
__device__ __align__(16) float g_A3[3 * FF * FF2];   // W3@T per layer = [A1 | A2]
__device__ __align__(16) float g_c[3 * FF];          // composed bias per layer
__device__ __align__(16) float g_Cfull[NN * FF2];    // [Y | Z+c]
__device__ __align__(16) float g_gA[NN * FF];        // node feats ping
__device__ __align__(16) float g_gB[NN * FF];        // node feats pong
__device__ __align__(16) float g_y[HH];              // hidden vector
__device__ unsigned g_adj[NN * 8];                   // bit j of row i => edge j->i

struct GemmBatch { const float* A[3]; const float* B[3]; float* C[3]; };
struct CvecBatch { const float* W2[3]; const float* b1[3]; const float* b2[3];
                   const float* W3[3]; const float* b3[3]; };

// ---------------- adjacency ----------------
__global__ void zero_adj_kernel(unsigned* adj) {
    int i = blockIdx.x * blockDim.x + threadIdx.x;
    if (i < NN * 8) adj[i] = 0u;
}

__global__ void scatter_adj_kernel(const int* __restrict__ ei, unsigned* __restrict__ adj) {
    int e = blockIdx.x * blockDim.x + threadIdx.x;
    if (e >= EE) return;
    int s = ei[e];          // src j
    int d = ei[EE + e];     // dst i
    atomicOr(&adj[(d << 3) + (s >> 5)], 1u << (s & 31));
}

// ---------------- batched 64x64-tile GEMM: C[z] = A[z] @ B[z] -----------------
// A[M,K], B[K,N] row-major. 256 threads, 4x4 micro-tile per thread.
__global__ __launch_bounds__(256) void gemm64_nn(GemmBatch p, int M, int N, int K) {
    int z = blockIdx.z;
    const float* __restrict__ A = p.A[z];
    const float* __restrict__ B = p.B[z];
    float* __restrict__ C = p.C[z];

    __shared__ float As[16][65];   // padded: kills 16-way store conflict
    __shared__ float Bs[16][64];

    int t  = threadIdx.x;
    int tx = t & 15, ty = t >> 4;
    int m0 = blockIdx.y * 64, n0 = blockIdx.x * 64;
    float acc[4][4] = {};

    for (int k0 = 0; k0 < K; k0 += 16) {
#pragma unroll
        for (int i = 0; i < 4; i++) {
            int idx = t + i * 256;
            int m = idx >> 4, k = idx & 15;
            int gm = m0 + m, gk = k0 + k;
            As[k][m] = (gm < M && gk < K) ? A[gm * K + gk] : 0.f;
        }
#pragma unroll
        for (int i = 0; i < 4; i++) {
            int idx = t + i * 256;
            int k = idx >> 6, n = idx & 63;
            int gk = k0 + k, gn = n0 + n;
            Bs[k][n] = (gk < K && gn < N) ? B[gk * N + gn] : 0.f;
        }
        __syncthreads();
#pragma unroll
        for (int k = 0; k < 16; k++) {
            float a0 = As[k][ty * 4 + 0];
            float a1 = As[k][ty * 4 + 1];
            float a2 = As[k][ty * 4 + 2];
            float a3 = As[k][ty * 4 + 3];
            float4 bv = *reinterpret_cast<const float4*>(&Bs[k][tx * 4]);
            acc[0][0] += a0 * bv.x; acc[0][1] += a0 * bv.y; acc[0][2] += a0 * bv.z; acc[0][3] += a0 * bv.w;
            acc[1][0] += a1 * bv.x; acc[1][1] += a1 * bv.y; acc[1][2] += a1 * bv.z; acc[1][3] += a1 * bv.w;
            acc[2][0] += a2 * bv.x; acc[2][1] += a2 * bv.y; acc[2][2] += a2 * bv.z; acc[2][3] += a2 * bv.w;
            acc[3][0] += a3 * bv.x; acc[3][1] += a3 * bv.y; acc[3][2] += a3 * bv.z; acc[3][3] += a3 * bv.w;
        }
        __syncthreads();
    }
#pragma unroll
    for (int i = 0; i < 4; i++) {
        int gm = m0 + ty * 4 + i;
        if (gm >= M) continue;
#pragma unroll
        for (int j = 0; j < 4; j++) {
            int gn = n0 + tx * 4 + j;
            if (gn < N) C[gm * N + gn] = acc[i][j];
        }
    }
}

// ---------------- NT GEMM with folded QP construction + bias -----------------
// Cfull[256,510] = gin[256,255] @ QP^T + [0 | c]
// QP row n (n<255):   Q_n  = A3[n, 255+k]
// QP row n (n>=255):  P_nr = A3[nr, k] - A3[nr, 255+k]   (nr = n-255)
__global__ __launch_bounds__(256) void gemm64_nt_fold(
    const float* __restrict__ gin, const float* __restrict__ A3l,
    const float* __restrict__ cl, float* __restrict__ C) {
    const int M = NN, N = FF2, K = FF;
    __shared__ float As[16][65];
    __shared__ float Bs[16][64];

    int t  = threadIdx.x;
    int tx = t & 15, ty = t >> 4;
    int m0 = blockIdx.y * 64, n0 = blockIdx.x * 64;
    float acc[4][4] = {};

    for (int k0 = 0; k0 < K; k0 += 16) {
#pragma unroll
        for (int i = 0; i < 4; i++) {
            int idx = t + i * 256;
            int m = idx >> 4, k = idx & 15;
            int gm = m0 + m, gk = k0 + k;
            As[k][m] = (gm < M && gk < K) ? gin[gm * K + gk] : 0.f;
        }
#pragma unroll
        for (int i = 0; i < 4; i++) {
            int idx = t + i * 256;
            int n = idx >> 4, k = idx & 15;   // 16 consecutive k per n: coalesced on A3 rows
            int gn = n0 + n, gk = k0 + k;
            float v = 0.f;
            if (gk < K) {
                if (gn < FF) {
                    v = A3l[gn * FF2 + FF + gk];                              // Q
                } else if (gn < FF2) {
                    int r = gn - FF;
                    v = A3l[r * FF2 + gk] - A3l[r * FF2 + FF + gk];           // P = A1-A2
                }
            }
            Bs[k][n] = v;
        }
        __syncthreads();
#pragma unroll
        for (int k = 0; k < 16; k++) {
            float a0 = As[k][ty * 4 + 0];
            float a1 = As[k][ty * 4 + 1];
            float a2 = As[k][ty * 4 + 2];
            float a3 = As[k][ty * 4 + 3];
            float4 bv = *reinterpret_cast<const float4*>(&Bs[k][tx * 4]);
            acc[0][0] += a0 * bv.x; acc[0][1] += a0 * bv.y; acc[0][2] += a0 * bv.z; acc[0][3] += a0 * bv.w;
            acc[1][0] += a1 * bv.x; acc[1][1] += a1 * bv.y; acc[1][2] += a1 * bv.z; acc[1][3] += a1 * bv.w;
            acc[2][0] += a2 * bv.x; acc[2][1] += a2 * bv.y; acc[2][2] += a2 * bv.z; acc[2][3] += a2 * bv.w;
            acc[3][0] += a3 * bv.x; acc[3][1] += a3 * bv.y; acc[3][2] += a3 * bv.z; acc[3][3] += a3 * bv.w;
        }
        __syncthreads();
    }
#pragma unroll
    for (int i = 0; i < 4; i++) {
        int gm = m0 + ty * 4 + i;
        if (gm >= M) continue;
#pragma unroll
        for (int j = 0; j < 4; j++) {
            int gn = n0 + tx * 4 + j;
            if (gn < N) {
                float bias = (gn >= FF) ? cl[gn - FF] : 0.f;
                C[gm * N + gn] = acc[i][j] + bias;
            }
        }
    }
}

// ---------------- batched bias composition: c = W3(W2 b1 + b2) + b3 ----------
__global__ void cvec_kernel(CvecBatch p, float* __restrict__ cout) {
    int z = blockIdx.x;
    __shared__ float u[FF];
    int t = threadIdx.x;
    if (t < FF) {
        float s = p.b2[z][t];
        const float* w2r = p.W2[z] + t * FF2;
        for (int k = 0; k < FF2; k++) s += w2r[k] * p.b1[z][k];
        u[t] = s;
    }
    __syncthreads();
    if (t < FF) {
        float s = p.b3[z][t];
        const float* w3r = p.W3[z] + t * FF;
        for (int k = 0; k < FF; k++) s += w3r[k] * u[k];
        cout[z * FF + t] = s;
    }
}

// ---------------- masked segment-max + combine + relu (+residual) ------------
__global__ void maxcombine_kernel(const float* __restrict__ Cfull,
                                  const unsigned* __restrict__ adj,
                                  const float* __restrict__ res,
                                  float* __restrict__ gout) {
    int i = blockIdx.x;
    int f = threadIdx.x;
    __shared__ unsigned rowm[8];
    if (threadIdx.x < 8) rowm[threadIdx.x] = adj[(i << 3) + threadIdx.x];
    __syncthreads();
    if (f >= FF) return;
    unsigned any = rowm[0] | rowm[1] | rowm[2] | rowm[3] | rowm[4] | rowm[5] | rowm[6] | rowm[7];

    float u = -FLT_MAX;
#pragma unroll 8
    for (int j = 0; j < NN; j++) {
        float v = __ldg(&Cfull[j * FF2 + f]);          // unconditional: pipelines
        unsigned bit = (rowm[j >> 5] >> (j & 31)) & 1u;
        u = fmaxf(u, bit ? v : -FLT_MAX);
    }
    float agg = (any == 0u) ? 0.f : (Cfull[i * FF2 + FF + f] + u);
    float r = res ? res[i * FF + f] : 0.f;
    gout[i * FF + f] = fmaxf(agg + r, 0.f);
}

// ---------------- y = relu(l4_W @ g3flat + l4_b) -----------------------------
// 2048 x 65280 matvec. 128 blocks x 512 thr; 16 rows/block (warp per row);
// x staged in SMEM in 16 tiles of 4080 floats -> x L2 traffic cut 16x.
__global__ __launch_bounds__(512) void matvec_l4_kernel(
    const float* __restrict__ W, const float* __restrict__ b,
    const float* __restrict__ x, float* __restrict__ y) {
    __shared__ __align__(16) float xs[4080];
    int warp = threadIdx.x >> 5, lane = threadIdx.x & 31;
    int row = blockIdx.x * 16 + warp;
    const float* Wrow = W + (size_t)row * NF;
    float acc = 0.f;

    for (int t = 0; t < 16; t++) {
        const float4* xg = reinterpret_cast<const float4*>(x + t * 4080);
        for (int i = threadIdx.x; i < 1020; i += 512)
            reinterpret_cast<float4*>(xs)[i] = xg[i];
        __syncthreads();
        const float4* Wv = reinterpret_cast<const float4*>(Wrow + t * 4080);
        const float4* xv = reinterpret_cast<const float4*>(xs);
#pragma unroll 8
        for (int k = lane; k < 1020; k += 32) {
            float4 w = Wv[k], v = xv[k];
            acc += w.x * v.x + w.y * v.y + w.z * v.z + w.w * v.w;
        }
        __syncthreads();
    }
#pragma unroll
    for (int o = 16; o > 0; o >>= 1) acc += __shfl_down_sync(0xffffffffu, acc, o);
    if (lane == 0) y[row] = fmaxf(acc + b[row], 0.f);
}

// ---------------- out = out_W @ y + out_b ------------------------------------
// 32640 x 2048; y staged in SMEM once per block (8 rows/block).
__global__ __launch_bounds__(256) void matvec_out_kernel(
    const float* __restrict__ W, const float* __restrict__ b,
    const float* __restrict__ y, float* __restrict__ out) {
    __shared__ __align__(16) float ys[HH];
    for (int i = threadIdx.x; i < HH / 4; i += 256)
        reinterpret_cast<float4*>(ys)[i] = reinterpret_cast<const float4*>(y)[i];
    __syncthreads();

    int warp = threadIdx.x >> 5, lane = threadIdx.x & 31;
    int row = blockIdx.x * 8 + warp;
    const float4* Wv = reinterpret_cast<const float4*>(W + (size_t)row * HH);
    const float4* yv = reinterpret_cast<const float4*>(ys);
    float acc = 0.f;
#pragma unroll
    for (int k = lane; k < HH / 4; k += 32) {
        float4 w = Wv[k], v = yv[k];
        acc += w.x * v.x + w.y * v.y + w.z * v.z + w.w * v.w;
    }
#pragma unroll
    for (int o = 16; o > 0; o >>= 1) acc += __shfl_down_sync(0xffffffffu, acc, o);
    if (lane == 0) out[row] = acc + b[row];
}

// =============================================================================
extern "C" void kernel_launch(void* const* d_in, const int* in_sizes, int n_in,
                              void* d_out, int out_size) {
    const float* x  = (const float*)d_in[0];
    const int*   ei = (const int*)d_in[1];

    const float* W[3][3];
    const float* B[3][3];
    int idx = 2;
    for (int l = 0; l < 3; l++)
        for (int m = 0; m < 3; m++) {
            W[l][m] = (const float*)d_in[idx++];
            B[l][m] = (const float*)d_in[idx++];
        }
    const float* l4W  = (const float*)d_in[20];
    const float* l4b  = (const float*)d_in[21];
    const float* outW = (const float*)d_in[22];
    const float* outb = (const float*)d_in[23];
    float* out = (float*)d_out;

    float *T, *A3, *cv, *Cfull, *gA, *gB, *y;
    unsigned* adj;
    cudaGetSymbolAddress((void**)&T,     g_T);
    cudaGetSymbolAddress((void**)&A3,    g_A3);
    cudaGetSymbolAddress((void**)&cv,    g_c);
    cudaGetSymbolAddress((void**)&Cfull, g_Cfull);
    cudaGetSymbolAddress((void**)&gA,    g_gA);
    cudaGetSymbolAddress((void**)&gB,    g_gB);
    cudaGetSymbolAddress((void**)&y,     g_y);
    cudaGetSymbolAddress((void**)&adj,   g_adj);

    // adjacency bitmask
    zero_adj_kernel<<<8, 256>>>(adj);
    scatter_adj_kernel<<<EE / 256, 256>>>(ei, adj);

    // --- weight-only precompute, all 3 layers batched ---
    GemmBatch pT, pA;
    CvecBatch pc;
    for (int l = 0; l < 3; l++) {
        pT.A[l] = W[l][1];          // W2 [255,510]
        pT.B[l] = W[l][0];          // W1 [510,510]
        pT.C[l] = T + l * FF * FF2;
        pA.A[l] = W[l][2];          // W3 [255,255]
        pA.B[l] = T + l * FF * FF2; // T  [255,510]
        pA.C[l] = A3 + l * FF * FF2;
        pc.W2[l] = W[l][1]; pc.b1[l] = B[l][0]; pc.b2[l] = B[l][1];
        pc.W3[l] = W[l][2]; pc.b3[l] = B[l][2];
    }
    {
        dim3 grid((FF2 + 63) / 64, (FF + 63) / 64, 3);   // 8 x 4 x 3
        gemm64_nn<<<grid, 256>>>(pT, FF, FF2, FF2);      // T = W2 @ W1
        gemm64_nn<<<grid, 256>>>(pA, FF, FF2, FF);       // A3 = W3 @ T
    }
    cvec_kernel<<<3, 256>>>(pc, cv);

    // --- sequential layer chain ---
    const float* gin = x;
    dim3 gridNT((FF2 + 63) / 64, (NN + 63) / 64);        // 8 x 4
    for (int l = 0; l < 3; l++) {
        gemm64_nt_fold<<<gridNT, 256>>>(gin, A3 + l * FF * FF2, cv + l * FF, Cfull);
        const float* res = (l == 0) ? nullptr : gin;
        float* gout = (l == 1) ? gB : gA;
        maxcombine_kernel<<<NN, 256>>>(Cfull, adj, res, gout);
        gin = gout;
    }

    // --- big mat-vecs ---
    matvec_l4_kernel<<<HH / 16, 512>>>(l4W, l4b, gin, y);
    matvec_out_kernel<<<OUTN / 8, 256>>>(outW, outb, y, out);
}

// round 5
// speedup vs baseline: 1.2866x; 1.2866x over previous
#include <cuda_runtime.h>
#include <cuda_bf16.h>
#include <cfloat>

// Problem constants
#define NN   256      // nodes
#define FF   255      // feature dim
#define FF2  510      // 2*F
#define EE   65536    // edges
#define HH   2048     // hidden
#define OUTN 32640    // output
#define NF   65280    // N*F (flatten)
#define KT   16       // k-tile

// ---------------- scratch (__device__ globals, no runtime alloc) -------------
__device__ __align__(16) float g_T[3 * FF * FF2];    // W2@W1 per layer
__device__ __align__(16) float g_A3[3 * FF * FF2];   // W3@T per layer = [A1 | A2]
__device__ __align__(16) float g_c[3 * FF];          // composed bias per layer
__device__ __align__(16) float g_Cfull[NN * FF2];    // [Y | Z+c]
__device__ __align__(16) float g_gA[NN * FF];        // node feats ping
__device__ __align__(16) float g_gB[NN * FF];        // node feats pong
__device__ __align__(16) float g_y[HH];              // hidden vector
__device__ unsigned g_adj[NN * 8];                   // bit j of row i => edge j->i

struct GemmBatch { const float* A[3]; const float* B[3]; float* C[3]; };
struct CvecBatch { const float* W2[3]; const float* b1[3]; const float* b2[3];
                   const float* W3[3]; const float* b3[3]; };

// ---------------- adjacency ----------------
__global__ void zero_adj_kernel(unsigned* adj) {
    int i = blockIdx.x * blockDim.x + threadIdx.x;
    if (i < NN * 8) adj[i] = 0u;
}

__global__ void scatter_adj_kernel(const int* __restrict__ ei, unsigned* __restrict__ adj) {
    int e = blockIdx.x * blockDim.x + threadIdx.x;
    if (e >= EE) return;
    int s = ei[e];          // src j
    int d = ei[EE + e];     // dst i
    atomicOr(&adj[(d << 3) + (s >> 5)], 1u << (s & 31));
}

// ---------------- batched 32x32-tile GEMM: C[z] = A[z] @ B[z] -----------------
// A[M,K], B[K,N] row-major. 256 threads, 2x2 micro-tile per thread.
__global__ __launch_bounds__(256) void gemm32_nn(GemmBatch p, int M, int N, int K) {
    int z = blockIdx.z;
    const float* __restrict__ A = p.A[z];
    const float* __restrict__ B = p.B[z];
    float* __restrict__ C = p.C[z];

    __shared__ float As[KT][33];   // As[k][m], stride 33 -> conflict-free stores
    __shared__ float Bs[KT][32];   // Bs[k][n]

    int t  = threadIdx.x;
    int tx = t & 15, ty = t >> 4;
    int m0 = blockIdx.y * 32, n0 = blockIdx.x * 32;
    float a00 = 0.f, a01 = 0.f, a10 = 0.f, a11 = 0.f;

    for (int k0 = 0; k0 < K; k0 += KT) {
#pragma unroll
        for (int i = 0; i < 2; i++) {
            int idx = t + i * 256;
            int m = idx >> 4, k = idx & 15;
            int gm = m0 + m, gk = k0 + k;
            As[k][m] = (gm < M && gk < K) ? A[gm * K + gk] : 0.f;
        }
#pragma unroll
        for (int i = 0; i < 2; i++) {
            int idx = t + i * 256;
            int k = idx >> 5, n = idx & 31;
            int gk = k0 + k, gn = n0 + n;
            Bs[k][n] = (gk < K && gn < N) ? B[gk * N + gn] : 0.f;
        }
        __syncthreads();
#pragma unroll
        for (int k = 0; k < KT; k++) {
            float x0 = As[k][ty * 2], x1 = As[k][ty * 2 + 1];
            float b0 = Bs[k][tx * 2], b1 = Bs[k][tx * 2 + 1];
            a00 += x0 * b0; a01 += x0 * b1;
            a10 += x1 * b0; a11 += x1 * b1;
        }
        __syncthreads();
    }
    int gm = m0 + ty * 2, gn = n0 + tx * 2;
    if (gm < M) {
        if (gn < N)     C[gm * N + gn]     = a00;
        if (gn + 1 < N) C[gm * N + gn + 1] = a01;
    }
    if (gm + 1 < M) {
        if (gn < N)     C[(gm + 1) * N + gn]     = a10;
        if (gn + 1 < N) C[(gm + 1) * N + gn + 1] = a11;
    }
}

// ---------------- NT GEMM with folded QP construction + bias -----------------
// Cfull[256,510] = gin[256,255] @ QP^T + [0 | c]
// QP row n (n<255):  Q_n = A3[n, 255+k];  n>=255: P = A3[nr,k]-A3[nr,255+k]
__global__ __launch_bounds__(256) void gemm32_nt_fold(
    const float* __restrict__ gin, const float* __restrict__ A3l,
    const float* __restrict__ cl, float* __restrict__ C) {
    const int M = NN, N = FF2, K = FF;
    __shared__ float As[KT][33];
    __shared__ float Bs[KT][33];

    int t  = threadIdx.x;
    int tx = t & 15, ty = t >> 4;
    int m0 = blockIdx.y * 32, n0 = blockIdx.x * 32;
    float a00 = 0.f, a01 = 0.f, a10 = 0.f, a11 = 0.f;

    for (int k0 = 0; k0 < K; k0 += KT) {
#pragma unroll
        for (int i = 0; i < 2; i++) {
            int idx = t + i * 256;
            int m = idx >> 4, k = idx & 15;
            int gm = m0 + m, gk = k0 + k;
            As[k][m] = (gm < M && gk < K) ? gin[gm * K + gk] : 0.f;
        }
#pragma unroll
        for (int i = 0; i < 2; i++) {
            int idx = t + i * 256;
            int n = idx >> 4, k = idx & 15;   // 16 consecutive k per n: coalesced
            int gn = n0 + n, gk = k0 + k;
            float v = 0.f;
            if (gk < K) {
                if (gn < FF) {
                    v = A3l[gn * FF2 + FF + gk];                     // Q
                } else if (gn < FF2) {
                    int r = gn - FF;
                    v = A3l[r * FF2 + gk] - A3l[r * FF2 + FF + gk];  // P = A1-A2
                }
            }
            Bs[k][n] = v;
        }
        __syncthreads();
#pragma unroll
        for (int k = 0; k < KT; k++) {
            float x0 = As[k][ty * 2], x1 = As[k][ty * 2 + 1];
            float b0 = Bs[k][tx * 2], b1 = Bs[k][tx * 2 + 1];
            a00 += x0 * b0; a01 += x0 * b1;
            a10 += x1 * b0; a11 += x1 * b1;
        }
        __syncthreads();
    }
    int gm = m0 + ty * 2, gn = n0 + tx * 2;
#pragma unroll
    for (int j = 0; j < 2; j++) {
        int n = gn + j;
        if (n >= N) continue;
        float bias = (n >= FF) ? cl[n - FF] : 0.f;
        float v0 = (j == 0) ? a00 : a01;
        float v1 = (j == 0) ? a10 : a11;
        if (gm < M)     C[gm * N + n]       = v0 + bias;
        if (gm + 1 < M) C[(gm + 1) * N + n] = v1 + bias;
    }
}

// ---------------- batched bias composition: c = W3(W2 b1 + b2) + b3 ----------
__global__ void cvec_kernel(CvecBatch p, float* __restrict__ cout) {
    int z = blockIdx.x;
    __shared__ float u[FF];
    int t = threadIdx.x;
    if (t < FF) {
        float s = p.b2[z][t];
        const float* w2r = p.W2[z] + t * FF2;
        for (int k = 0; k < FF2; k++) s += w2r[k] * p.b1[z][k];
        u[t] = s;
    }
    __syncthreads();
    if (t < FF) {
        float s = p.b3[z][t];
        const float* w3r = p.W3[z] + t * FF;
        for (int k = 0; k < FF; k++) s += w3r[k] * u[k];
        cout[z * FF + t] = s;
    }
}

// ---------------- masked segment-max + combine + relu (+residual) ------------
__global__ void maxcombine_kernel(const float* __restrict__ Cfull,
                                  const unsigned* __restrict__ adj,
                                  const float* __restrict__ res,
                                  float* __restrict__ gout) {
    int i = blockIdx.x;
    int f = threadIdx.x;
    __shared__ unsigned rowm[8];
    if (threadIdx.x < 8) rowm[threadIdx.x] = adj[(i << 3) + threadIdx.x];
    __syncthreads();
    if (f >= FF) return;
    unsigned any = rowm[0] | rowm[1] | rowm[2] | rowm[3] | rowm[4] | rowm[5] | rowm[6] | rowm[7];

    float u = -FLT_MAX;
#pragma unroll 8
    for (int j = 0; j < NN; j++) {
        float v = __ldg(&Cfull[j * FF2 + f]);          // unconditional: pipelines
        unsigned bit = (rowm[j >> 5] >> (j & 31)) & 1u;
        u = fmaxf(u, bit ? v : -FLT_MAX);
    }
    float agg = (any == 0u) ? 0.f : (Cfull[i * FF2 + FF + f] + u);
    float r = res ? res[i * FF + f] : 0.f;
    gout[i * FF + f] = fmaxf(agg + r, 0.f);
}

// ---------------- y = relu(l4_W @ g3flat + l4_b) -----------------------------
// 2048 x 65280 matvec. 256 blocks x 256 thr; 8 rows/block (warp per row);
// x staged in SMEM in 16 tiles of 4080 floats -> x L2 traffic cut 8x.
__global__ __launch_bounds__(256) void matvec_l4_kernel(
    const float* __restrict__ W, const float* __restrict__ b,
    const float* __restrict__ x, float* __restrict__ y) {
    __shared__ __align__(16) float xs[4080];
    int warp = threadIdx.x >> 5, lane = threadIdx.x & 31;
    int row = blockIdx.x * 8 + warp;
    const float* Wrow = W + (size_t)row * NF;
    float acc = 0.f;

    for (int t = 0; t < 16; t++) {
        const float4* xg = reinterpret_cast<const float4*>(x + t * 4080);
        for (int i = threadIdx.x; i < 1020; i += 256)
            reinterpret_cast<float4*>(xs)[i] = xg[i];
        __syncthreads();
        const float4* Wv = reinterpret_cast<const float4*>(Wrow + t * 4080);
        const float4* xv = reinterpret_cast<const float4*>(xs);
#pragma unroll 8
        for (int k = lane; k < 1020; k += 32) {
            float4 w = Wv[k], v = xv[k];
            acc += w.x * v.x + w.y * v.y + w.z * v.z + w.w * v.w;
        }
        __syncthreads();
    }
#pragma unroll
    for (int o = 16; o > 0; o >>= 1) acc += __shfl_down_sync(0xffffffffu, acc, o);
    if (lane == 0) y[row] = fmaxf(acc + b[row], 0.f);
}

// ---------------- out = out_W @ y + out_b ------------------------------------
// 32640 x 2048; y staged in SMEM once per block (8 rows/block).
__global__ __launch_bounds__(256) void matvec_out_kernel(
    const float* __restrict__ W, const float* __restrict__ b,
    const float* __restrict__ y, float* __restrict__ out) {
    __shared__ __align__(16) float ys[HH];
    for (int i = threadIdx.x; i < HH / 4; i += 256)
        reinterpret_cast<float4*>(ys)[i] = reinterpret_cast<const float4*>(y)[i];
    __syncthreads();

    int warp = threadIdx.x >> 5, lane = threadIdx.x & 31;
    int row = blockIdx.x * 8 + warp;
    const float4* Wv = reinterpret_cast<const float4*>(W + (size_t)row * HH);
    const float4* yv = reinterpret_cast<const float4*>(ys);
    float acc = 0.f;
#pragma unroll
    for (int k = lane; k < HH / 4; k += 32) {
        float4 w = Wv[k], v = yv[k];
        acc += w.x * v.x + w.y * v.y + w.z * v.z + w.w * v.w;
    }
#pragma unroll
    for (int o = 16; o > 0; o >>= 1) acc += __shfl_down_sync(0xffffffffu, acc, o);
    if (lane == 0) out[row] = acc + b[row];
}

// =============================================================================
extern "C" void kernel_launch(void* const* d_in, const int* in_sizes, int n_in,
                              void* d_out, int out_size) {
    const float* x  = (const float*)d_in[0];
    const int*   ei = (const int*)d_in[1];

    const float* W[3][3];
    const float* B[3][3];
    int idx = 2;
    for (int l = 0; l < 3; l++)
        for (int m = 0; m < 3; m++) {
            W[l][m] = (const float*)d_in[idx++];
            B[l][m] = (const float*)d_in[idx++];
        }
    const float* l4W  = (const float*)d_in[20];
    const float* l4b  = (const float*)d_in[21];
    const float* outW = (const float*)d_in[22];
    const float* outb = (const float*)d_in[23];
    float* out = (float*)d_out;

    float *T, *A3, *cv, *Cfull, *gA, *gB, *y;
    unsigned* adj;
    cudaGetSymbolAddress((void**)&T,     g_T);
    cudaGetSymbolAddress((void**)&A3,    g_A3);
    cudaGetSymbolAddress((void**)&cv,    g_c);
    cudaGetSymbolAddress((void**)&Cfull, g_Cfull);
    cudaGetSymbolAddress((void**)&gA,    g_gA);
    cudaGetSymbolAddress((void**)&gB,    g_gB);
    cudaGetSymbolAddress((void**)&y,     g_y);
    cudaGetSymbolAddress((void**)&adj,   g_adj);

    // adjacency bitmask
    zero_adj_kernel<<<8, 256>>>(adj);
    scatter_adj_kernel<<<EE / 256, 256>>>(ei, adj);

    // --- weight-only precompute, all 3 layers batched ---
    GemmBatch pT, pA;
    CvecBatch pc;
    for (int l = 0; l < 3; l++) {
        pT.A[l] = W[l][1];          // W2 [255,510]
        pT.B[l] = W[l][0];          // W1 [510,510]
        pT.C[l] = T + l * FF * FF2;
        pA.A[l] = W[l][2];          // W3 [255,255]
        pA.B[l] = T + l * FF * FF2; // T  [255,510]
        pA.C[l] = A3 + l * FF * FF2;
        pc.W2[l] = W[l][1]; pc.b1[l] = B[l][0]; pc.b2[l] = B[l][1];
        pc.W3[l] = W[l][2]; pc.b3[l] = B[l][2];
    }
    {
        dim3 grid((FF2 + 31) / 32, (FF + 31) / 32, 3);   // 16 x 8 x 3 = 384
        gemm32_nn<<<grid, 256>>>(pT, FF, FF2, FF2);      // T = W2 @ W1
        gemm32_nn<<<grid, 256>>>(pA, FF, FF2, FF);       // A3 = W3 @ T
    }
    cvec_kernel<<<3, 256>>>(pc, cv);

    // --- sequential layer chain ---
    const float* gin = x;
    dim3 gridNT((FF2 + 31) / 32, (NN + 31) / 32);        // 16 x 8 = 128
    for (int l = 0; l < 3; l++) {
        gemm32_nt_fold<<<gridNT, 256>>>(gin, A3 + l * FF * FF2, cv + l * FF, Cfull);
        const float* res = (l == 0) ? nullptr : gin;
        float* gout = (l == 1) ? gB : gA;
        maxcombine_kernel<<<NN, 256>>>(Cfull, adj, res, gout);
        gin = gout;
    }

    // --- big mat-vecs ---
    matvec_l4_kernel<<<HH / 8, 256>>>(l4W, l4b, gin, y);
    matvec_out_kernel<<<OUTN / 8, 256>>>(outW, outb, y, out);
}

// round 6
// speedup vs baseline: 1.3902x; 1.0805x over previous
#include <cuda_runtime.h>
#include <cuda_bf16.h>
#include <cfloat>

// Problem constants
#define NN   256      // nodes
#define FF   255      // feature dim
#define FF2  510      // 2*F
#define EE   65536    // edges
#define HH   2048     // hidden
#define OUTN 32640    // output
#define NF   65280    // N*F (flatten)
#define KT   32       // k-tile

// ---------------- scratch (__device__ globals, no runtime alloc) -------------
__device__ __align__(16) float g_T[3 * FF * FF2];    // W2@W1 per layer
__device__ __align__(16) float g_A3[3 * FF * FF2];   // W3@T per layer = [A1 | A2]
__device__ __align__(16) float g_u[3 * FF];          // W2@b1+b2 per layer
__device__ __align__(16) float g_c[3 * FF];          // composed bias per layer
__device__ __align__(16) float g_Cfull[NN * FF2];    // [Y | Z+c]
__device__ __align__(16) float g_gA[NN * FF];        // node feats ping
__device__ __align__(16) float g_gB[NN * FF];        // node feats pong
__device__ __align__(16) float g_y[HH];              // hidden vector
__device__ unsigned g_adj[NN * 8];                   // bit j of row i => edge j->i

struct GemmBatch { const float* A[3]; const float* B[3]; float* C[3]; };
struct MatBatch  { const float* M[3]; const float* v[3]; const float* b[3]; };

// ---------------- adjacency ----------------
__global__ void zero_adj_kernel(unsigned* adj) {
    int i = blockIdx.x * blockDim.x + threadIdx.x;
    if (i < NN * 8) adj[i] = 0u;
}

__global__ void scatter_adj_kernel(const int* __restrict__ ei, unsigned* __restrict__ adj) {
    int e = blockIdx.x * blockDim.x + threadIdx.x;
    if (e >= EE) return;
    int s = ei[e];          // src j
    int d = ei[EE + e];     // dst i
    atomicOr(&adj[(d << 3) + (s >> 5)], 1u << (s & 31));
}

// ---------------- batched 32x32-tile GEMM: C[z] = A[z] @ B[z] -----------------
// A[M,K], B[K,N] row-major. 256 threads, 2x2 micro-tile, float2 LDS.
__global__ __launch_bounds__(256) void gemm32_nn(GemmBatch p, int M, int N, int K) {
    int z = blockIdx.z;
    const float* __restrict__ A = p.A[z];
    const float* __restrict__ B = p.B[z];
    float* __restrict__ C = p.C[z];

    __shared__ __align__(16) float As[KT][34];   // As[k][m]
    __shared__ __align__(16) float Bs[KT][34];   // Bs[k][n]

    int t  = threadIdx.x;
    int tx = t & 15, ty = t >> 4;
    int m0 = blockIdx.y * 32, n0 = blockIdx.x * 32;
    float a00 = 0.f, a01 = 0.f, a10 = 0.f, a11 = 0.f;

    for (int k0 = 0; k0 < K; k0 += KT) {
#pragma unroll
        for (int i = 0; i < 4; i++) {
            int idx = t + i * 256;
            int m = idx >> 5, k = idx & 31;     // k fast -> coalesced A read
            int gm = m0 + m, gk = k0 + k;
            As[k][m] = (gm < M && gk < K) ? A[gm * K + gk] : 0.f;
        }
#pragma unroll
        for (int i = 0; i < 4; i++) {
            int idx = t + i * 256;
            int k = idx >> 5, n = idx & 31;     // n fast -> coalesced B read
            int gk = k0 + k, gn = n0 + n;
            Bs[k][n] = (gk < K && gn < N) ? B[gk * N + gn] : 0.f;
        }
        __syncthreads();
#pragma unroll
        for (int k = 0; k < KT; k++) {
            float2 av = *reinterpret_cast<const float2*>(&As[k][ty * 2]);
            float2 bv = *reinterpret_cast<const float2*>(&Bs[k][tx * 2]);
            a00 += av.x * bv.x; a01 += av.x * bv.y;
            a10 += av.y * bv.x; a11 += av.y * bv.y;
        }
        __syncthreads();
    }
    int gm = m0 + ty * 2, gn = n0 + tx * 2;
    if (gm < M) {
        if (gn < N)     C[gm * N + gn]     = a00;
        if (gn + 1 < N) C[gm * N + gn + 1] = a01;
    }
    if (gm + 1 < M) {
        if (gn < N)     C[(gm + 1) * N + gn]     = a10;
        if (gn + 1 < N) C[(gm + 1) * N + gn + 1] = a11;
    }
}

// ---------------- NT GEMM with folded QP construction + bias -----------------
// Cfull[256,510] = gin[256,255] @ QP^T + [0 | c]
// QP row n (n<255):  Q_n = A3[n, 255+k];  n>=255: P = A3[nr,k]-A3[nr,255+k]
__global__ __launch_bounds__(256) void gemm32_nt_fold(
    const float* __restrict__ gin, const float* __restrict__ A3l,
    const float* __restrict__ cl, float* __restrict__ C) {
    const int M = NN, N = FF2, K = FF;
    __shared__ __align__(16) float As[KT][34];
    __shared__ __align__(16) float Bs[KT][34];

    int t  = threadIdx.x;
    int tx = t & 15, ty = t >> 4;
    int m0 = blockIdx.y * 32, n0 = blockIdx.x * 32;
    float a00 = 0.f, a01 = 0.f, a10 = 0.f, a11 = 0.f;

    for (int k0 = 0; k0 < K; k0 += KT) {
#pragma unroll
        for (int i = 0; i < 4; i++) {
            int idx = t + i * 256;
            int m = idx >> 5, k = idx & 31;
            int gm = m0 + m, gk = k0 + k;
            As[k][m] = (gm < M && gk < K) ? gin[gm * K + gk] : 0.f;
        }
#pragma unroll
        for (int i = 0; i < 4; i++) {
            int idx = t + i * 256;
            int n = idx >> 5, k = idx & 31;     // k fast -> coalesced A3 row read
            int gn = n0 + n, gk = k0 + k;
            float v = 0.f;
            if (gk < K) {
                if (gn < FF) {
                    v = A3l[gn * FF2 + FF + gk];                     // Q
                } else if (gn < FF2) {
                    int r = gn - FF;
                    v = A3l[r * FF2 + gk] - A3l[r * FF2 + FF + gk];  // P = A1-A2
                }
            }
            Bs[k][n] = v;
        }
        __syncthreads();
#pragma unroll
        for (int k = 0; k < KT; k++) {
            float2 av = *reinterpret_cast<const float2*>(&As[k][ty * 2]);
            float2 bv = *reinterpret_cast<const float2*>(&Bs[k][tx * 2]);
            a00 += av.x * bv.x; a01 += av.x * bv.y;
            a10 += av.y * bv.x; a11 += av.y * bv.y;
        }
        __syncthreads();
    }
    int gm = m0 + ty * 2, gn = n0 + tx * 2;
#pragma unroll
    for (int j = 0; j < 2; j++) {
        int n = gn + j;
        if (n >= N) continue;
        float bias = (n >= FF) ? cl[n - FF] : 0.f;
        float v0 = (j == 0) ? a00 : a01;
        float v1 = (j == 0) ? a10 : a11;
        if (gm < M)     C[gm * N + n]       = v0 + bias;
        if (gm + 1 < M) C[(gm + 1) * N + n] = v1 + bias;
    }
}

// ---------------- coalesced bias composition -----------------
// Phase 1: u[z][t] = b2[t] + W2[t,:] . b1   (warp per row, lanes along k)
__global__ __launch_bounds__(256) void uvec_kernel(MatBatch p, float* __restrict__ uout) {
    int z = blockIdx.y;
    int warp = threadIdx.x >> 5, lane = threadIdx.x & 31;
    const float* W2 = p.M[z];
    const float* b1 = p.v[z];
    const float* b2 = p.b[z];
#pragma unroll
    for (int r = 0; r < 4; r++) {
        int row = blockIdx.x * 32 + warp * 4 + r;
        if (row >= FF) continue;
        float s = 0.f;
        for (int k = lane; k < FF2; k += 32)
            s += W2[row * FF2 + k] * b1[k];
#pragma unroll
        for (int o = 16; o > 0; o >>= 1) s += __shfl_down_sync(0xffffffffu, s, o);
        if (lane == 0) uout[z * FF + row] = s + b2[row];
    }
}

// Phase 2: c[z][t] = b3[t] + W3[t,:] . u[z,:]
__global__ __launch_bounds__(256) void cvec_kernel(MatBatch p, const float* __restrict__ u,
                                                   float* __restrict__ cout) {
    int z = blockIdx.y;
    int warp = threadIdx.x >> 5, lane = threadIdx.x & 31;
    const float* W3 = p.M[z];
    const float* b3 = p.b[z];
#pragma unroll
    for (int r = 0; r < 4; r++) {
        int row = blockIdx.x * 32 + warp * 4 + r;
        if (row >= FF) continue;
        float s = 0.f;
        for (int k = lane; k < FF; k += 32)
            s += W3[row * FF + k] * u[z * FF + k];
#pragma unroll
        for (int o = 16; o > 0; o >>= 1) s += __shfl_down_sync(0xffffffffu, s, o);
        if (lane == 0) cout[z * FF + row] = s + b3[row];
    }
}

// ---------------- masked segment-max + combine + relu (+residual) ------------
__global__ void maxcombine_kernel(const float* __restrict__ Cfull,
                                  const unsigned* __restrict__ adj,
                                  const float* __restrict__ res,
                                  float* __restrict__ gout) {
    int i = blockIdx.x;
    int f = threadIdx.x;
    __shared__ unsigned rowm[8];
    if (threadIdx.x < 8) rowm[threadIdx.x] = adj[(i << 3) + threadIdx.x];
    __syncthreads();
    if (f >= FF) return;
    unsigned any = rowm[0] | rowm[1] | rowm[2] | rowm[3] | rowm[4] | rowm[5] | rowm[6] | rowm[7];

    float u = -FLT_MAX;
#pragma unroll 8
    for (int j = 0; j < NN; j++) {
        float v = __ldg(&Cfull[j * FF2 + f]);          // unconditional: pipelines
        unsigned bit = (rowm[j >> 5] >> (j & 31)) & 1u;
        u = fmaxf(u, bit ? v : -FLT_MAX);
    }
    float agg = (any == 0u) ? 0.f : (Cfull[i * FF2 + FF + f] + u);
    float r = res ? res[i * FF + f] : 0.f;
    gout[i * FF + f] = fmaxf(agg + r, 0.f);
}

// ---------------- y = relu(l4_W @ g3flat + l4_b) -----------------------------
// 2048 x 65280 matvec; 8 rows/block (warp per row); x staged via SMEM tiles.
__global__ __launch_bounds__(256) void matvec_l4_kernel(
    const float* __restrict__ W, const float* __restrict__ b,
    const float* __restrict__ x, float* __restrict__ y) {
    __shared__ __align__(16) float xs[4080];
    int warp = threadIdx.x >> 5, lane = threadIdx.x & 31;
    int row = blockIdx.x * 8 + warp;
    const float* Wrow = W + (size_t)row * NF;
    float acc = 0.f;

    for (int t = 0; t < 16; t++) {
        const float4* xg = reinterpret_cast<const float4*>(x + t * 4080);
        for (int i = threadIdx.x; i < 1020; i += 256)
            reinterpret_cast<float4*>(xs)[i] = xg[i];
        __syncthreads();
        const float4* Wv = reinterpret_cast<const float4*>(Wrow + t * 4080);
        const float4* xv = reinterpret_cast<const float4*>(xs);
#pragma unroll 8
        for (int k = lane; k < 1020; k += 32) {
            float4 w = Wv[k], v = xv[k];
            acc += w.x * v.x + w.y * v.y + w.z * v.z + w.w * v.w;
        }
        __syncthreads();
    }
#pragma unroll
    for (int o = 16; o > 0; o >>= 1) acc += __shfl_down_sync(0xffffffffu, acc, o);
    if (lane == 0) y[row] = fmaxf(acc + b[row], 0.f);
}

// ---------------- out = out_W @ y + out_b ------------------------------------
__global__ __launch_bounds__(256) void matvec_out_kernel(
    const float* __restrict__ W, const float* __restrict__ b,
    const float* __restrict__ y, float* __restrict__ out) {
    __shared__ __align__(16) float ys[HH];
    for (int i = threadIdx.x; i < HH / 4; i += 256)
        reinterpret_cast<float4*>(ys)[i] = reinterpret_cast<const float4*>(y)[i];
    __syncthreads();

    int warp = threadIdx.x >> 5, lane = threadIdx.x & 31;
    int row = blockIdx.x * 8 + warp;
    const float4* Wv = reinterpret_cast<const float4*>(W + (size_t)row * HH);
    const float4* yv = reinterpret_cast<const float4*>(ys);
    float acc = 0.f;
#pragma unroll
    for (int k = lane; k < HH / 4; k += 32) {
        float4 w = Wv[k], v = yv[k];
        acc += w.x * v.x + w.y * v.y + w.z * v.z + w.w * v.w;
    }
#pragma unroll
    for (int o = 16; o > 0; o >>= 1) acc += __shfl_down_sync(0xffffffffu, acc, o);
    if (lane == 0) out[row] = acc + b[row];
}

// =============================================================================
extern "C" void kernel_launch(void* const* d_in, const int* in_sizes, int n_in,
                              void* d_out, int out_size) {
    const float* x  = (const float*)d_in[0];
    const int*   ei = (const int*)d_in[1];

    const float* W[3][3];
    const float* B[3][3];
    int idx = 2;
    for (int l = 0; l < 3; l++)
        for (int m = 0; m < 3; m++) {
            W[l][m] = (const float*)d_in[idx++];
            B[l][m] = (const float*)d_in[idx++];
        }
    const float* l4W  = (const float*)d_in[20];
    const float* l4b  = (const float*)d_in[21];
    const float* outW = (const float*)d_in[22];
    const float* outb = (const float*)d_in[23];
    float* out = (float*)d_out;

    float *T, *A3, *uv, *cv, *Cfull, *gA, *gB, *y;
    unsigned* adj;
    cudaGetSymbolAddress((void**)&T,     g_T);
    cudaGetSymbolAddress((void**)&A3,    g_A3);
    cudaGetSymbolAddress((void**)&uv,    g_u);
    cudaGetSymbolAddress((void**)&cv,    g_c);
    cudaGetSymbolAddress((void**)&Cfull, g_Cfull);
    cudaGetSymbolAddress((void**)&gA,    g_gA);
    cudaGetSymbolAddress((void**)&gB,    g_gB);
    cudaGetSymbolAddress((void**)&y,     g_y);
    cudaGetSymbolAddress((void**)&adj,   g_adj);

    // adjacency bitmask
    zero_adj_kernel<<<8, 256>>>(adj);
    scatter_adj_kernel<<<EE / 256, 256>>>(ei, adj);

    // --- weight-only precompute, all 3 layers batched ---
    GemmBatch pT, pA;
    MatBatch pu, pcv;
    for (int l = 0; l < 3; l++) {
        pT.A[l] = W[l][1];          // W2 [255,510]
        pT.B[l] = W[l][0];          // W1 [510,510]
        pT.C[l] = T + l * FF * FF2;
        pA.A[l] = W[l][2];          // W3 [255,255]
        pA.B[l] = T + l * FF * FF2; // T  [255,510]
        pA.C[l] = A3 + l * FF * FF2;
        pu.M[l] = W[l][1]; pu.v[l] = B[l][0]; pu.b[l] = B[l][1];
        pcv.M[l] = W[l][2]; pcv.v[l] = nullptr; pcv.b[l] = B[l][2];
    }
    {
        dim3 grid((FF2 + 31) / 32, (FF + 31) / 32, 3);   // 16 x 8 x 3 = 384
        gemm32_nn<<<grid, 256>>>(pT, FF, FF2, FF2);      // T = W2 @ W1
        gemm32_nn<<<grid, 256>>>(pA, FF, FF2, FF);       // A3 = W3 @ T
    }
    {
        dim3 gridc(8, 3);
        uvec_kernel<<<gridc, 256>>>(pu, uv);
        cvec_kernel<<<gridc, 256>>>(pcv, uv, cv);
    }

    // --- sequential layer chain ---
    const float* gin = x;
    dim3 gridNT((FF2 + 31) / 32, (NN + 31) / 32);        // 16 x 8 = 128
    for (int l = 0; l < 3; l++) {
        gemm32_nt_fold<<<gridNT, 256>>>(gin, A3 + l * FF * FF2, cv + l * FF, Cfull);
        const float* res = (l == 0) ? nullptr : gin;
        float* gout = (l == 1) ? gB : gA;
        maxcombine_kernel<<<NN, 256>>>(Cfull, adj, res, gout);
        gin = gout;
    }

    // --- big mat-vecs ---
    matvec_l4_kernel<<<HH / 8, 256>>>(l4W, l4b, gin, y);
    matvec_out_kernel<<<OUTN / 8, 256>>>(outW, outb, y, out);
}

// round 7
// speedup vs baseline: 1.3911x; 1.0007x over previous
#include <cuda_runtime.h>
#include <cuda_bf16.h>
#include <cfloat>

// Problem constants
#define NN   256      // nodes
#define FF   255      // feature dim
#define FF2  510      // 2*F
#define EE   65536    // edges
#define HH   2048     // hidden
#define OUTN 32640    // output
#define NF   65280    // N*F (flatten)
#define KT   32       // k-tile

// ---------------- scratch (__device__ globals, no runtime alloc) -------------
__device__ __align__(16) float g_T[3 * FF * FF2];    // W2@W1 per layer
__device__ __align__(16) float g_A3[3 * FF * FF2];   // W3@T per layer = [A1 | A2]
__device__ __align__(16) float g_u[3 * FF];          // W2@b1+b2 per layer
__device__ __align__(16) float g_c[3 * FF];          // composed bias per layer
__device__ __align__(16) float g_Cfull[NN * FF2];    // [Y | Z+c]
__device__ __align__(16) float g_gA[NN * FF];        // node feats ping
__device__ __align__(16) float g_gB[NN * FF];        // node feats pong
__device__ __align__(16) float g_y[HH];              // hidden vector
__device__ unsigned g_adj[NN * 8];                   // bit j of row i => edge j->i

struct GemmBatch { const float* A[3]; const float* B[3]; float* C[3]; };
struct MatBatch  { const float* M[3]; const float* v[3]; const float* b[3]; };

// ---------------- adjacency ----------------
__global__ void zero_adj_kernel(unsigned* adj) {
    int i = blockIdx.x * blockDim.x + threadIdx.x;
    if (i < NN * 8) adj[i] = 0u;
}

__global__ void scatter_adj_kernel(const int* __restrict__ ei, unsigned* __restrict__ adj) {
    int e = blockIdx.x * blockDim.x + threadIdx.x;
    if (e >= EE) return;
    int s = ei[e];          // src j
    int d = ei[EE + e];     // dst i
    atomicOr(&adj[(d << 3) + (s >> 5)], 1u << (s & 31));
}

// ---------------- batched 32x32-tile GEMM: C[z] = A[z] @ B[z] -----------------
// A[M,K], B[K,N] row-major. 256 threads, 2x2 micro-tile, float2 LDS.
__global__ __launch_bounds__(256) void gemm32_nn(GemmBatch p, int M, int N, int K) {
    int z = blockIdx.z;
    const float* __restrict__ A = p.A[z];
    const float* __restrict__ B = p.B[z];
    float* __restrict__ C = p.C[z];

    __shared__ __align__(16) float As[KT][34];   // As[k][m]
    __shared__ __align__(16) float Bs[KT][34];   // Bs[k][n]

    int t  = threadIdx.x;
    int tx = t & 15, ty = t >> 4;
    int m0 = blockIdx.y * 32, n0 = blockIdx.x * 32;
    float a00 = 0.f, a01 = 0.f, a10 = 0.f, a11 = 0.f;

    for (int k0 = 0; k0 < K; k0 += KT) {
#pragma unroll
        for (int i = 0; i < 4; i++) {
            int idx = t + i * 256;
            int m = idx >> 5, k = idx & 31;     // k fast -> coalesced A read
            int gm = m0 + m, gk = k0 + k;
            As[k][m] = (gm < M && gk < K) ? A[gm * K + gk] : 0.f;
        }
#pragma unroll
        for (int i = 0; i < 4; i++) {
            int idx = t + i * 256;
            int k = idx >> 5, n = idx & 31;     // n fast -> coalesced B read
            int gk = k0 + k, gn = n0 + n;
            Bs[k][n] = (gk < K && gn < N) ? B[gk * N + gn] : 0.f;
        }
        __syncthreads();
#pragma unroll
        for (int k = 0; k < KT; k++) {
            float2 av = *reinterpret_cast<const float2*>(&As[k][ty * 2]);
            float2 bv = *reinterpret_cast<const float2*>(&Bs[k][tx * 2]);
            a00 += av.x * bv.x; a01 += av.x * bv.y;
            a10 += av.y * bv.x; a11 += av.y * bv.y;
        }
        __syncthreads();
    }
    int gm = m0 + ty * 2, gn = n0 + tx * 2;
    if (gm < M) {
        if (gn < N)     C[gm * N + gn]     = a00;
        if (gn + 1 < N) C[gm * N + gn + 1] = a01;
    }
    if (gm + 1 < M) {
        if (gn < N)     C[(gm + 1) * N + gn]     = a10;
        if (gn + 1 < N) C[(gm + 1) * N + gn + 1] = a11;
    }
}

// ---------------- NT GEMM with folded QP construction + bias -----------------
// Cfull[256,510] = gin[256,255] @ QP^T + [0 | c]
// QP row n (n<255):  Q_n = A3[n, 255+k];  n>=255: P = A3[nr,k]-A3[nr,255+k]
__global__ __launch_bounds__(256) void gemm32_nt_fold(
    const float* __restrict__ gin, const float* __restrict__ A3l,
    const float* __restrict__ cl, float* __restrict__ C) {
    const int M = NN, N = FF2, K = FF;
    __shared__ __align__(16) float As[KT][34];
    __shared__ __align__(16) float Bs[KT][34];

    int t  = threadIdx.x;
    int tx = t & 15, ty = t >> 4;
    int m0 = blockIdx.y * 32, n0 = blockIdx.x * 32;
    float a00 = 0.f, a01 = 0.f, a10 = 0.f, a11 = 0.f;

    for (int k0 = 0; k0 < K; k0 += KT) {
#pragma unroll
        for (int i = 0; i < 4; i++) {
            int idx = t + i * 256;
            int m = idx >> 5, k = idx & 31;
            int gm = m0 + m, gk = k0 + k;
            As[k][m] = (gm < M && gk < K) ? gin[gm * K + gk] : 0.f;
        }
#pragma unroll
        for (int i = 0; i < 4; i++) {
            int idx = t + i * 256;
            int n = idx >> 5, k = idx & 31;     // k fast -> coalesced A3 row read
            int gn = n0 + n, gk = k0 + k;
            float v = 0.f;
            if (gk < K) {
                if (gn < FF) {
                    v = A3l[gn * FF2 + FF + gk];                     // Q
                } else if (gn < FF2) {
                    int r = gn - FF;
                    v = A3l[r * FF2 + gk] - A3l[r * FF2 + FF + gk];  // P = A1-A2
                }
            }
            Bs[k][n] = v;
        }
        __syncthreads();
#pragma unroll
        for (int k = 0; k < KT; k++) {
            float2 av = *reinterpret_cast<const float2*>(&As[k][ty * 2]);
            float2 bv = *reinterpret_cast<const float2*>(&Bs[k][tx * 2]);
            a00 += av.x * bv.x; a01 += av.x * bv.y;
            a10 += av.y * bv.x; a11 += av.y * bv.y;
        }
        __syncthreads();
    }
    int gm = m0 + ty * 2, gn = n0 + tx * 2;
#pragma unroll
    for (int j = 0; j < 2; j++) {
        int n = gn + j;
        if (n >= N) continue;
        float bias = (n >= FF) ? cl[n - FF] : 0.f;
        float v0 = (j == 0) ? a00 : a01;
        float v1 = (j == 0) ? a10 : a11;
        if (gm < M)     C[gm * N + n]       = v0 + bias;
        if (gm + 1 < M) C[(gm + 1) * N + n] = v1 + bias;
    }
}

// ---------------- coalesced bias composition -----------------
// Phase 1: u[z][t] = b2[t] + W2[t,:] . b1   (warp per row, lanes along k)
__global__ __launch_bounds__(256) void uvec_kernel(MatBatch p, float* __restrict__ uout) {
    int z = blockIdx.y;
    int warp = threadIdx.x >> 5, lane = threadIdx.x & 31;
    const float* W2 = p.M[z];
    const float* b1 = p.v[z];
    const float* b2 = p.b[z];
#pragma unroll
    for (int r = 0; r < 4; r++) {
        int row = blockIdx.x * 32 + warp * 4 + r;
        if (row >= FF) continue;
        float s = 0.f;
        for (int k = lane; k < FF2; k += 32)
            s += W2[row * FF2 + k] * b1[k];
#pragma unroll
        for (int o = 16; o > 0; o >>= 1) s += __shfl_down_sync(0xffffffffu, s, o);
        if (lane == 0) uout[z * FF + row] = s + b2[row];
    }
}

// Phase 2: c[z][t] = b3[t] + W3[t,:] . u[z,:]
__global__ __launch_bounds__(256) void cvec_kernel(MatBatch p, const float* __restrict__ u,
                                                   float* __restrict__ cout) {
    int z = blockIdx.y;
    int warp = threadIdx.x >> 5, lane = threadIdx.x & 31;
    const float* W3 = p.M[z];
    const float* b3 = p.b[z];
#pragma unroll
    for (int r = 0; r < 4; r++) {
        int row = blockIdx.x * 32 + warp * 4 + r;
        if (row >= FF) continue;
        float s = 0.f;
        for (int k = lane; k < FF; k += 32)
            s += W3[row * FF + k] * u[z * FF + k];
#pragma unroll
        for (int o = 16; o > 0; o >>= 1) s += __shfl_down_sync(0xffffffffu, s, o);
        if (lane == 0) cout[z * FF + row] = s + b3[row];
    }
}

// ---------------- masked segment-max + combine + relu (+residual) ------------
__global__ void maxcombine_kernel(const float* __restrict__ Cfull,
                                  const unsigned* __restrict__ adj,
                                  const float* __restrict__ res,
                                  float* __restrict__ gout) {
    int i = blockIdx.x;
    int f = threadIdx.x;
    __shared__ unsigned rowm[8];
    if (threadIdx.x < 8) rowm[threadIdx.x] = adj[(i << 3) + threadIdx.x];
    __syncthreads();
    if (f >= FF) return;
    unsigned any = rowm[0] | rowm[1] | rowm[2] | rowm[3] | rowm[4] | rowm[5] | rowm[6] | rowm[7];

    float u = -FLT_MAX;
#pragma unroll 8
    for (int j = 0; j < NN; j++) {
        float v = __ldg(&Cfull[j * FF2 + f]);          // unconditional: pipelines
        unsigned bit = (rowm[j >> 5] >> (j & 31)) & 1u;
        u = fmaxf(u, bit ? v : -FLT_MAX);
    }
    float agg = (any == 0u) ? 0.f : (Cfull[i * FF2 + FF + f] + u);
    float r = res ? res[i * FF + f] : 0.f;
    gout[i * FF + f] = fmaxf(agg + r, 0.f);
}

// ---------------- y = relu(l4_W @ g3flat + l4_b) -----------------------------
// 2048 x 65280 matvec; 8 rows/block (warp per row); x staged via SMEM tiles.
__global__ __launch_bounds__(256) void matvec_l4_kernel(
    const float* __restrict__ W, const float* __restrict__ b,
    const float* __restrict__ x, float* __restrict__ y) {
    __shared__ __align__(16) float xs[4080];
    int warp = threadIdx.x >> 5, lane = threadIdx.x & 31;
    int row = blockIdx.x * 8 + warp;
    const float* Wrow = W + (size_t)row * NF;
    float acc = 0.f;

    for (int t = 0; t < 16; t++) {
        const float4* xg = reinterpret_cast<const float4*>(x + t * 4080);
        for (int i = threadIdx.x; i < 1020; i += 256)
            reinterpret_cast<float4*>(xs)[i] = xg[i];
        __syncthreads();
        const float4* Wv = reinterpret_cast<const float4*>(Wrow + t * 4080);
        const float4* xv = reinterpret_cast<const float4*>(xs);
#pragma unroll 8
        for (int k = lane; k < 1020; k += 32) {
            float4 w = Wv[k], v = xv[k];
            acc += w.x * v.x + w.y * v.y + w.z * v.z + w.w * v.w;
        }
        __syncthreads();
    }
#pragma unroll
    for (int o = 16; o > 0; o >>= 1) acc += __shfl_down_sync(0xffffffffu, acc, o);
    if (lane == 0) y[row] = fmaxf(acc + b[row], 0.f);
}

// ---------------- out = out_W @ y + out_b ------------------------------------
__global__ __launch_bounds__(256) void matvec_out_kernel(
    const float* __restrict__ W, const float* __restrict__ b,
    const float* __restrict__ y, float* __restrict__ out) {
    __shared__ __align__(16) float ys[HH];
    for (int i = threadIdx.x; i < HH / 4; i += 256)
        reinterpret_cast<float4*>(ys)[i] = reinterpret_cast<const float4*>(y)[i];
    __syncthreads();

    int warp = threadIdx.x >> 5, lane = threadIdx.x & 31;
    int row = blockIdx.x * 8 + warp;
    const float4* Wv = reinterpret_cast<const float4*>(W + (size_t)row * HH);
    const float4* yv = reinterpret_cast<const float4*>(ys);
    float acc = 0.f;
#pragma unroll
    for (int k = lane; k < HH / 4; k += 32) {
        float4 w = Wv[k], v = yv[k];
        acc += w.x * v.x + w.y * v.y + w.z * v.z + w.w * v.w;
    }
#pragma unroll
    for (int o = 16; o > 0; o >>= 1) acc += __shfl_down_sync(0xffffffffu, acc, o);
    if (lane == 0) out[row] = acc + b[row];
}

// =============================================================================
extern "C" void kernel_launch(void* const* d_in, const int* in_sizes, int n_in,
                              void* d_out, int out_size) {
    const float* x  = (const float*)d_in[0];
    const int*   ei = (const int*)d_in[1];

    const float* W[3][3];
    const float* B[3][3];
    int idx = 2;
    for (int l = 0; l < 3; l++)
        for (int m = 0; m < 3; m++) {
            W[l][m] = (const float*)d_in[idx++];
            B[l][m] = (const float*)d_in[idx++];
        }
    const float* l4W  = (const float*)d_in[20];
    const float* l4b  = (const float*)d_in[21];
    const float* outW = (const float*)d_in[22];
    const float* outb = (const float*)d_in[23];
    float* out = (float*)d_out;

    float *T, *A3, *uv, *cv, *Cfull, *gA, *gB, *y;
    unsigned* adj;
    cudaGetSymbolAddress((void**)&T,     g_T);
    cudaGetSymbolAddress((void**)&A3,    g_A3);
    cudaGetSymbolAddress((void**)&uv,    g_u);
    cudaGetSymbolAddress((void**)&cv,    g_c);
    cudaGetSymbolAddress((void**)&Cfull, g_Cfull);
    cudaGetSymbolAddress((void**)&gA,    g_gA);
    cudaGetSymbolAddress((void**)&gB,    g_gB);
    cudaGetSymbolAddress((void**)&y,     g_y);
    cudaGetSymbolAddress((void**)&adj,   g_adj);

    // adjacency bitmask
    zero_adj_kernel<<<8, 256>>>(adj);
    scatter_adj_kernel<<<EE / 256, 256>>>(ei, adj);

    // --- weight-only precompute, all 3 layers batched ---
    GemmBatch pT, pA;
    MatBatch pu, pcv;
    for (int l = 0; l < 3; l++) {
        pT.A[l] = W[l][1];          // W2 [255,510]
        pT.B[l] = W[l][0];          // W1 [510,510]
        pT.C[l] = T + l * FF * FF2;
        pA.A[l] = W[l][2];          // W3 [255,255]
        pA.B[l] = T + l * FF * FF2; // T  [255,510]
        pA.C[l] = A3 + l * FF * FF2;
        pu.M[l] = W[l][1]; pu.v[l] = B[l][0]; pu.b[l] = B[l][1];
        pcv.M[l] = W[l][2]; pcv.v[l] = nullptr; pcv.b[l] = B[l][2];
    }
    {
        dim3 grid((FF2 + 31) / 32, (FF + 31) / 32, 3);   // 16 x 8 x 3 = 384
        gemm32_nn<<<grid, 256>>>(pT, FF, FF2, FF2);      // T = W2 @ W1
        gemm32_nn<<<grid, 256>>>(pA, FF, FF2, FF);       // A3 = W3 @ T
    }
    {
        dim3 gridc(8, 3);
        uvec_kernel<<<gridc, 256>>>(pu, uv);
        cvec_kernel<<<gridc, 256>>>(pcv, uv, cv);
    }

    // --- sequential layer chain ---
    const float* gin = x;
    dim3 gridNT((FF2 + 31) / 32, (NN + 31) / 32);        // 16 x 8 = 128
    for (int l = 0; l < 3; l++) {
        gemm32_nt_fold<<<gridNT, 256>>>(gin, A3 + l * FF * FF2, cv + l * FF, Cfull);
        const float* res = (l == 0) ? nullptr : gin;
        float* gout = (l == 1) ? gB : gA;
        maxcombine_kernel<<<NN, 256>>>(Cfull, adj, res, gout);
        gin = gout;
    }

    // --- big mat-vecs ---
    matvec_l4_kernel<<<HH / 8, 256>>>(l4W, l4b, gin, y);
    matvec_out_kernel<<<OUTN / 8, 256>>>(outW, outb, y, out);
}